// round 8
// baseline (speedup 1.0000x reference)
#include <cuda_runtime.h>
#include <cuda_bf16.h>
#include <cstdint>
#include <cstring>

#define SEQ 4096
#define TQ  64
#define WIN 256
#define NB  4

// smem byte offsets: bf16 K-hi, K-lo, V-hi, V-lo (8KB each), then fp32 staging
#define KH 0
#define KL 8192
#define VH 16384
#define VL 24576
#define SG 32768
#define SG_ROW 272                       // 17*16B, odd 16B-units -> conflict-free
#define SG_V   (SG + 64 * SG_ROW)        // V staging
#define SMEM_TOTAL (SG + 2 * 64 * SG_ROW)   // 67584

// key-split scratch: z=1 half's unnormalized partials + flags
__device__ float    g_osc[(size_t)NB * SEQ * 64];
__device__ float    g_lsc[NB * SEQ];
__device__ unsigned g_flag[NB * 64];

__device__ __forceinline__ uint32_t smem_u32(const void* p) {
    uint32_t a;
    asm("{ .reg .u64 t; cvta.to.shared.u64 t, %1; cvt.u32.u64 %0, t; }" : "=r"(a) : "l"(p));
    return a;
}
__device__ __forceinline__ float ex2(float x) {
    float r; asm("ex2.approx.ftz.f32 %0, %1;" : "=f"(r) : "f"(x)); return r;
}
__device__ __forceinline__ void ldsm4(uint32_t& r0, uint32_t& r1, uint32_t& r2, uint32_t& r3, uint32_t a) {
    asm volatile("ldmatrix.sync.aligned.m8n8.x4.shared.b16 {%0,%1,%2,%3}, [%4];"
                 : "=r"(r0), "=r"(r1), "=r"(r2), "=r"(r3) : "r"(a));
}
__device__ __forceinline__ void ldsm4t(uint32_t& r0, uint32_t& r1, uint32_t& r2, uint32_t& r3, uint32_t a) {
    asm volatile("ldmatrix.sync.aligned.m8n8.x4.trans.shared.b16 {%0,%1,%2,%3}, [%4];"
                 : "=r"(r0), "=r"(r1), "=r"(r2), "=r"(r3) : "r"(a));
}
__device__ __forceinline__ void mma4(float (&d)[4], uint32_t a0, uint32_t a1, uint32_t a2, uint32_t a3,
                                     uint32_t b0, uint32_t b1) {
    asm volatile("mma.sync.aligned.m16n8k16.row.col.f32.bf16.bf16.f32 "
                 "{%0,%1,%2,%3}, {%4,%5,%6,%7}, {%8,%9}, {%0,%1,%2,%3};"
                 : "+f"(d[0]), "+f"(d[1]), "+f"(d[2]), "+f"(d[3])
                 : "r"(a0), "r"(a1), "r"(a2), "r"(a3), "r"(b0), "r"(b1));
}
__device__ __forceinline__ uint32_t packbf(float x, float y) {
    __nv_bfloat162 v = __floats2bfloat162_rn(x, y);
    uint32_t u; memcpy(&u, &v, 4); return u;
}
__device__ __forceinline__ void splitp(float x, float y, uint32_t& h, uint32_t& l) {
    __nv_bfloat16 hx = __float2bfloat16(x), hy = __float2bfloat16(y);
    h = ((uint32_t)__bfloat16_as_ushort(hy) << 16) | __bfloat16_as_ushort(hx);
    l = packbf(x - __bfloat162float(hx), y - __bfloat162float(hy));
}

// async prefetch of a 64-key fp32 K/V tile into staging
__device__ __forceinline__ void prefetch_tile(uint32_t sbu, const float* qkv_b, int k0, int tid) {
    int r = tid & 63, isV = tid >> 6;
    const char* g = reinterpret_cast<const char*>(qkv_b + (size_t)(k0 + r) * 192 + 64 + isV * 64);
    uint32_t s = sbu + (isV ? SG_V : SG) + r * SG_ROW;
    #pragma unroll
    for (int c = 0; c < 16; c++)
        asm volatile("cp.async.cg.shared.global [%0], [%1], 16;"
                     :: "r"(s + c * 16), "l"(g + c * 16));
    asm volatile("cp.async.commit_group;" ::: "memory");
}

// convert staged fp32 tile -> bf16 hi/lo (swizzled, same layout as R6)
__device__ __forceinline__ void convert_tile(char* smc, int tid) {
    int r = tid & 63, isV = tid >> 6;
    const char* st = smc + (isV ? SG_V : SG) + r * SG_ROW;
    char* hb = smc + (isV ? VH : KH) + r * 128;
    char* lb = smc + (isV ? VL : KL) + r * 128;
    uint32_t xr = (r & 7) << 4;
    #pragma unroll
    for (int gi = 0; gi < 8; gi++) {
        float4 f0 = *reinterpret_cast<const float4*>(st + gi * 32);
        float4 f1 = *reinterpret_cast<const float4*>(st + gi * 32 + 16);
        uint4 hv, lv;
        splitp(f0.x, f0.y, hv.x, lv.x);
        splitp(f0.z, f0.w, hv.y, lv.y);
        splitp(f1.x, f1.y, hv.z, lv.z);
        splitp(f1.z, f1.w, hv.w, lv.w);
        uint32_t off = (uint32_t)(gi * 16) ^ xr;
        *reinterpret_cast<uint4*>(hb + off) = hv;
        *reinterpret_cast<uint4*>(lb + off) = lv;
    }
}

// MODE: 0 unmasked, 1 diagonal (valid j<=iq), 2 lowest (valid j>=iq-WIN)
template<int MODE>
__device__ __forceinline__ void compute_tile(int k0, int tid, uint32_t sbu,
                                             const uint32_t (&qh)[4][4], const uint32_t (&ql)[4][4],
                                             float (&o)[8][4], float& l0acc, float& l1acc,
                                             int iq0, int iq1)
{
    const int lane = tid & 31, w = tid >> 5;
    const int t = lane & 3;
    const int rk = lane & 7;
    const uint32_t xorl = rk << 4;
    const uint32_t m16  = (lane >> 3) * 16;

    // ---- S = Q·K^T (split bf16: Qh*Kh + Ql*Kh + Qh*Kl) ----
    float s[8][4] = {};
    #pragma unroll
    for (int c = 0; c < 4; c += 2) {
        #pragma unroll
        for (int nt = 0; nt < 8; nt++) {
            if (MODE == 1 && nt >= 2 * w + 2) continue;
            if (MODE == 2 && nt < 2 * w) continue;
            uint32_t base = sbu + (uint32_t)(nt * 1024 + rk * 128) + ((uint32_t)(c * 32 + m16) ^ xorl);
            uint32_t kh0, kh1, kh2, kh3, kl0, kl1, kl2, kl3;
            ldsm4(kh0, kh1, kh2, kh3, base + KH);
            ldsm4(kl0, kl1, kl2, kl3, base + KL);
            mma4(s[nt], qh[c][0], qh[c][1], qh[c][2], qh[c][3], kh0, kh1);
            mma4(s[nt], qh[c+1][0], qh[c+1][1], qh[c+1][2], qh[c+1][3], kh2, kh3);
            mma4(s[nt], ql[c][0], ql[c][1], ql[c][2], ql[c][3], kh0, kh1);
            mma4(s[nt], ql[c+1][0], ql[c+1][1], ql[c+1][2], ql[c+1][3], kh2, kh3);
            mma4(s[nt], qh[c][0], qh[c][1], qh[c][2], qh[c][3], kl0, kl1);
            mma4(s[nt], qh[c+1][0], qh[c+1][1], qh[c+1][2], qh[c+1][3], kl2, kl3);
        }
    }

    // ---- softmax (static max): p = valid ? 2^s : 0; split to bf16 hi/lo ----
    uint32_t ph[8], phB[8], pl[8], plB[8];
    #pragma unroll
    for (int nt = 0; nt < 8; nt++) {
        int j0 = k0 + nt * 8 + 2 * t, j1 = j0 + 1;
        bool v00 = true, v01 = true, v10 = true, v11 = true;
        if (MODE == 1) { v00 = j0 <= iq0; v01 = j1 <= iq0; v10 = j0 <= iq1; v11 = j1 <= iq1; }
        if (MODE == 2) { v00 = j0 >= iq0 - WIN; v01 = j1 >= iq0 - WIN;
                         v10 = j0 >= iq1 - WIN; v11 = j1 >= iq1 - WIN; }
        float p0 = v00 ? ex2(s[nt][0]) : 0.0f;
        float p1 = v01 ? ex2(s[nt][1]) : 0.0f;
        float p2 = v10 ? ex2(s[nt][2]) : 0.0f;
        float p3 = v11 ? ex2(s[nt][3]) : 0.0f;
        l0acc += p0 + p1;
        l1acc += p2 + p3;
        splitp(p0, p1, ph[nt], pl[nt]);
        splitp(p2, p3, phB[nt], plB[nt]);
    }

    // ---- O += P·V (split bf16), V via ldmatrix.trans ----
    const int matk = (lane >> 3) & 1, matn = lane >> 4;
    #pragma unroll
    for (int ck = 0; ck < 4; ck++) {
        if (MODE == 1 && ck > w) continue;
        if (MODE == 2 && ck < w) continue;
        uint32_t A0 = ph[2*ck], A1 = phB[2*ck], A2 = ph[2*ck+1], A3 = phB[2*ck+1];
        uint32_t L0 = pl[2*ck], L1 = plB[2*ck], L2 = pl[2*ck+1], L3 = plB[2*ck+1];
        uint32_t rowoff = (uint32_t)((ck * 16 + matk * 8 + rk) * 128);
        #pragma unroll
        for (int ntd = 0; ntd < 8; ntd += 2) {
            uint32_t base = sbu + rowoff + ((uint32_t)((ntd + matn) * 16) ^ xorl);
            uint32_t vh0, vh1, vh2, vh3, vl0, vl1, vl2, vl3;
            ldsm4t(vh0, vh1, vh2, vh3, base + VH);
            ldsm4t(vl0, vl1, vl2, vl3, base + VL);
            mma4(o[ntd],     A0, A1, A2, A3, vh0, vh1);
            mma4(o[ntd + 1], A0, A1, A2, A3, vh2, vh3);
            mma4(o[ntd],     L0, L1, L2, L3, vh0, vh1);
            mma4(o[ntd + 1], L0, L1, L2, L3, vh2, vh3);
            mma4(o[ntd],     A0, A1, A2, A3, vl0, vl1);
            mma4(o[ntd + 1], A0, A1, A2, A3, vl2, vl3);
        }
    }
}

__global__ __launch_bounds__(128, 3) void swa_mma(const float* __restrict__ qkv,
                                                  float* __restrict__ out)
{
    extern __shared__ __align__(1024) char smc[];
    const uint32_t sbu = smem_u32(smc);
    const int tid = threadIdx.x, lane = tid & 31, w = tid >> 5;
    const int g = lane >> 2, t = lane & 3;
    const int qt = blockIdx.x >> 1, z = blockIdx.x & 1;   // pair-adjacent halves
    const int b = blockIdx.y, q0 = qt * TQ;
    const float* qkv_b = qkv + (size_t)b * SEQ * 192;

    const int iq0 = q0 + w * 16 + g, iq1 = iq0 + 8;
    const int fq = b * 64 + qt;

    // ---- load Q fragments, scaled, split bf16 hi/lo ----
    const float SCL = 0.125f * 1.44269504088896f;
    uint32_t qh[4][4], ql[4][4];
    {
        const float* qp0 = qkv_b + (size_t)iq0 * 192;
        const float* qp1 = qkv_b + (size_t)iq1 * 192;
        #pragma unroll
        for (int c = 0; c < 4; c++) {
            float2 x0 = *reinterpret_cast<const float2*>(qp0 + c * 16 + 2 * t);
            float2 x1 = *reinterpret_cast<const float2*>(qp1 + c * 16 + 2 * t);
            float2 x2 = *reinterpret_cast<const float2*>(qp0 + c * 16 + 2 * t + 8);
            float2 x3 = *reinterpret_cast<const float2*>(qp1 + c * 16 + 2 * t + 8);
            splitp(x0.x * SCL, x0.y * SCL, qh[c][0], ql[c][0]);
            splitp(x1.x * SCL, x1.y * SCL, qh[c][1], ql[c][1]);
            splitp(x2.x * SCL, x2.y * SCL, qh[c][2], ql[c][2]);
            splitp(x3.x * SCL, x3.y * SCL, qh[c][3], ql[c][3]);
        }
    }

    float o[8][4] = {};
    float l0 = 0.0f, l1 = 0.0f;

    const int kstart = q0 >= WIN ? q0 - WIN : 0;
    const int n = (q0 - kstart) / 64 + 1;
    const int myn = (n - z + 1) / 2;            // my tiles: i = z, z+2, ...

    if (myn > 0) {
        prefetch_tile(sbu, qkv_b, kstart + 64 * z, tid);
        for (int j = 0; j < myn; j++) {
            int i = z + 2 * j, k0 = kstart + 64 * i;
            asm volatile("cp.async.wait_group 0;" ::: "memory");
            __syncthreads();                    // staging ready; prev tile consumed
            convert_tile(smc, tid);
            __syncthreads();                    // bf16 ready; staging free
            if (j + 1 < myn)
                prefetch_tile(sbu, qkv_b, kstart + 64 * (i + 2), tid);
            if (q0 >= WIN && i == 0)
                compute_tile<2>(k0, tid, sbu, qh, ql, o, l0, l1, iq0, iq1);
            else if (k0 == q0)
                compute_tile<1>(k0, tid, sbu, qh, ql, o, l0, l1, iq0, iq1);
            else
                compute_tile<0>(k0, tid, sbu, qh, ql, o, l0, l1, iq0, iq1);
        }
    }

    // ---- reduce l across the 4 lanes sharing a row ----
    l0 += __shfl_xor_sync(0xffffffffu, l0, 1);
    l0 += __shfl_xor_sync(0xffffffffu, l0, 2);
    l1 += __shfl_xor_sync(0xffffffffu, l1, 1);
    l1 += __shfl_xor_sync(0xffffffffu, l1, 2);

    if (z == 1) {
        // publish partials, then flag
        if (t == 0) {
            g_lsc[b * SEQ + iq0] = l0;
            g_lsc[b * SEQ + iq1] = l1;
        }
        float* o0 = g_osc + ((size_t)(b * SEQ + iq0)) * 64 + 2 * t;
        float* o1 = g_osc + ((size_t)(b * SEQ + iq1)) * 64 + 2 * t;
        #pragma unroll
        for (int nt = 0; nt < 8; nt++) {
            *reinterpret_cast<float2*>(o0 + nt * 8) = make_float2(o[nt][0], o[nt][1]);
            *reinterpret_cast<float2*>(o1 + nt * 8) = make_float2(o[nt][2], o[nt][3]);
        }
        __threadfence();
        __syncthreads();
        if (tid == 0)
            asm volatile("st.release.gpu.global.b32 [%0], %1;"
                         :: "l"(&g_flag[fq]), "r"(1u) : "memory");
    } else {
        // wait for partner, combine, normalize, store
        if (tid == 0) {
            unsigned v;
            do {
                asm volatile("ld.acquire.gpu.global.b32 %0, [%1];"
                             : "=r"(v) : "l"(&g_flag[fq]) : "memory");
            } while (v == 0);
            g_flag[fq] = 0;                    // reset for next graph replay
        }
        __syncthreads();
        float lp0 = g_lsc[b * SEQ + iq0], lp1 = g_lsc[b * SEQ + iq1];
        float rl0 = 1.0f / (l0 + lp0), rl1 = 1.0f / (l1 + lp1);
        const float* p0 = g_osc + ((size_t)(b * SEQ + iq0)) * 64 + 2 * t;
        const float* p1 = g_osc + ((size_t)(b * SEQ + iq1)) * 64 + 2 * t;
        float* o0 = out + (size_t)(b * SEQ + iq0) * 64 + 2 * t;
        float* o1 = out + (size_t)(b * SEQ + iq1) * 64 + 2 * t;
        #pragma unroll
        for (int nt = 0; nt < 8; nt++) {
            float2 a = *reinterpret_cast<const float2*>(p0 + nt * 8);
            float2 c = *reinterpret_cast<const float2*>(p1 + nt * 8);
            *reinterpret_cast<float2*>(o0 + nt * 8) =
                make_float2((o[nt][0] + a.x) * rl0, (o[nt][1] + a.y) * rl0);
            *reinterpret_cast<float2*>(o1 + nt * 8) =
                make_float2((o[nt][2] + c.x) * rl1, (o[nt][3] + c.y) * rl1);
        }
    }
}

extern "C" void kernel_launch(void* const* d_in, const int* in_sizes, int n_in,
                              void* d_out, int out_size)
{
    const float* qkv = (const float*)d_in[0];
    float* out = (float*)d_out;
    int B = in_sizes[0] / (SEQ * 192);
    static bool configured = false;
    if (!configured) {
        cudaFuncSetAttribute(swa_mma, cudaFuncAttributeMaxDynamicSharedMemorySize, SMEM_TOTAL);
        configured = true;
    }
    dim3 grid(2 * SEQ / TQ, B);
    swa_mma<<<grid, 128, SMEM_TOTAL>>>(qkv, out);
}

// round 9
// speedup vs baseline: 1.6028x; 1.6028x over previous
#include <cuda_runtime.h>
#include <cuda_bf16.h>
#include <cstdint>
#include <cstring>

#define SEQ 4096
#define TQ  64
#define WIN 256
#define NB  4

// per-buffer smem offsets (bf16 tiles, swizzled images)
#define KH 0
#define KL 8192
#define VH 16384
#define VL 24576
#define BUF 32768
#define SMEM_TOTAL (2 * BUF)

// precomputed bf16 hi/lo K/V tiles, stored as exact swizzled smem images:
// [b][tile][ KH | KL | VH | VL ] = 32KB per 64-key tile
__device__ char g_kv[(size_t)NB * (SEQ / 64) * BUF];

__device__ __forceinline__ uint32_t smem_u32(const void* p) {
    uint32_t a;
    asm("{ .reg .u64 t; cvta.to.shared.u64 t, %1; cvt.u32.u64 %0, t; }" : "=r"(a) : "l"(p));
    return a;
}
__device__ __forceinline__ float ex2(float x) {
    float r; asm("ex2.approx.ftz.f32 %0, %1;" : "=f"(r) : "f"(x)); return r;
}
__device__ __forceinline__ void ldsm4(uint32_t& r0, uint32_t& r1, uint32_t& r2, uint32_t& r3, uint32_t a) {
    asm volatile("ldmatrix.sync.aligned.m8n8.x4.shared.b16 {%0,%1,%2,%3}, [%4];"
                 : "=r"(r0), "=r"(r1), "=r"(r2), "=r"(r3) : "r"(a));
}
__device__ __forceinline__ void ldsm4t(uint32_t& r0, uint32_t& r1, uint32_t& r2, uint32_t& r3, uint32_t a) {
    asm volatile("ldmatrix.sync.aligned.m8n8.x4.trans.shared.b16 {%0,%1,%2,%3}, [%4];"
                 : "=r"(r0), "=r"(r1), "=r"(r2), "=r"(r3) : "r"(a));
}
__device__ __forceinline__ void mma4(float (&d)[4], uint32_t a0, uint32_t a1, uint32_t a2, uint32_t a3,
                                     uint32_t b0, uint32_t b1) {
    asm volatile("mma.sync.aligned.m16n8k16.row.col.f32.bf16.bf16.f32 "
                 "{%0,%1,%2,%3}, {%4,%5,%6,%7}, {%8,%9}, {%0,%1,%2,%3};"
                 : "+f"(d[0]), "+f"(d[1]), "+f"(d[2]), "+f"(d[3])
                 : "r"(a0), "r"(a1), "r"(a2), "r"(a3), "r"(b0), "r"(b1));
}
__device__ __forceinline__ uint32_t packbf(float x, float y) {
    __nv_bfloat162 v = __floats2bfloat162_rn(x, y);
    uint32_t u; memcpy(&u, &v, 4); return u;
}
__device__ __forceinline__ void splitp(float x, float y, uint32_t& h, uint32_t& l) {
    __nv_bfloat16 hx = __float2bfloat16(x), hy = __float2bfloat16(y);
    h = ((uint32_t)__bfloat16_as_ushort(hy) << 16) | __bfloat16_as_ushort(hx);
    l = packbf(x - __bfloat162float(hx), y - __bfloat162float(hy));
}

// ---- precompute: fp32 K/V -> bf16 hi/lo swizzled tile images (once) ----
__global__ __launch_bounds__(128) void conv_kernel(const float* __restrict__ qkv)
{
    const int ti = blockIdx.x, b = blockIdx.y, tid = threadIdx.x;
    const int r = tid & 63, isV = tid >> 6;
    const float4* src = reinterpret_cast<const float4*>(
        qkv + ((size_t)b * SEQ + ti * 64 + r) * 192 + 64 + isV * 64);
    char* base = g_kv + ((size_t)(b * (SEQ / 64) + ti)) * BUF + (isV ? VH : KH);
    char* hb = base + r * 128;
    char* lb = base + 8192 + r * 128;
    const uint32_t xr = (r & 7) << 4;
    #pragma unroll
    for (int gi = 0; gi < 8; gi++) {
        float4 f0 = src[2 * gi], f1 = src[2 * gi + 1];
        uint4 hv, lv;
        splitp(f0.x, f0.y, hv.x, lv.x);
        splitp(f0.z, f0.w, hv.y, lv.y);
        splitp(f1.x, f1.y, hv.z, lv.z);
        splitp(f1.z, f1.w, hv.w, lv.w);
        uint32_t off = (uint32_t)(gi * 16) ^ xr;
        *reinterpret_cast<uint4*>(hb + off) = hv;
        *reinterpret_cast<uint4*>(lb + off) = lv;
    }
}

// async copy of one precomputed 32KB tile image into an smem buffer
__device__ __forceinline__ void prefetch_tile(uint32_t dst, const char* src, int tid) {
    #pragma unroll
    for (int c = 0; c < 16; c++) {
        uint32_t off = (uint32_t)(tid * 16 + c * 2048);
        asm volatile("cp.async.cg.shared.global [%0], [%1], 16;"
                     :: "r"(dst + off), "l"(src + off));
    }
    asm volatile("cp.async.commit_group;" ::: "memory");
}

// MODE: 0 unmasked, 1 diagonal (valid j<=iq), 2 lowest (valid j>=iq-WIN)
template<int MODE>
__device__ __forceinline__ void compute_tile(int k0, int tid, uint32_t sb,
                                             const uint32_t (&qh)[4][4], const uint32_t (&ql)[4][4],
                                             float (&o)[8][4], float& l0acc, float& l1acc,
                                             int iq0, int iq1)
{
    const int lane = tid & 31, w = tid >> 5;
    const int t = lane & 3;
    const int rk = lane & 7;
    const uint32_t xorl = rk << 4;
    const uint32_t m16  = (lane >> 3) * 16;

    // ---- S = Q·K^T (split bf16: Qh*Kh + Ql*Kh + Qh*Kl) ----
    float s[8][4] = {};
    #pragma unroll
    for (int c = 0; c < 4; c += 2) {
        #pragma unroll
        for (int nt = 0; nt < 8; nt++) {
            if (MODE == 1 && nt >= 2 * w + 2) continue;
            if (MODE == 2 && nt < 2 * w) continue;
            uint32_t base = sb + (uint32_t)(nt * 1024 + rk * 128) + ((uint32_t)(c * 32 + m16) ^ xorl);
            uint32_t kh0, kh1, kh2, kh3, kl0, kl1, kl2, kl3;
            ldsm4(kh0, kh1, kh2, kh3, base + KH);
            ldsm4(kl0, kl1, kl2, kl3, base + KL);
            mma4(s[nt], qh[c][0], qh[c][1], qh[c][2], qh[c][3], kh0, kh1);
            mma4(s[nt], qh[c+1][0], qh[c+1][1], qh[c+1][2], qh[c+1][3], kh2, kh3);
            mma4(s[nt], ql[c][0], ql[c][1], ql[c][2], ql[c][3], kh0, kh1);
            mma4(s[nt], ql[c+1][0], ql[c+1][1], ql[c+1][2], ql[c+1][3], kh2, kh3);
            mma4(s[nt], qh[c][0], qh[c][1], qh[c][2], qh[c][3], kl0, kl1);
            mma4(s[nt], qh[c+1][0], qh[c+1][1], qh[c+1][2], qh[c+1][3], kl2, kl3);
        }
    }

    // ---- softmax (static max): p = valid ? 2^s : 0; split to bf16 hi/lo ----
    uint32_t ph[8], phB[8], pl[8], plB[8];
    #pragma unroll
    for (int nt = 0; nt < 8; nt++) {
        int j0 = k0 + nt * 8 + 2 * t, j1 = j0 + 1;
        bool v00 = true, v01 = true, v10 = true, v11 = true;
        if (MODE == 1) { v00 = j0 <= iq0; v01 = j1 <= iq0; v10 = j0 <= iq1; v11 = j1 <= iq1; }
        if (MODE == 2) { v00 = j0 >= iq0 - WIN; v01 = j1 >= iq0 - WIN;
                         v10 = j0 >= iq1 - WIN; v11 = j1 >= iq1 - WIN; }
        float p0 = v00 ? ex2(s[nt][0]) : 0.0f;
        float p1 = v01 ? ex2(s[nt][1]) : 0.0f;
        float p2 = v10 ? ex2(s[nt][2]) : 0.0f;
        float p3 = v11 ? ex2(s[nt][3]) : 0.0f;
        l0acc += p0 + p1;
        l1acc += p2 + p3;
        splitp(p0, p1, ph[nt], pl[nt]);
        splitp(p2, p3, phB[nt], plB[nt]);
    }

    // ---- O += P·V (split bf16), V via ldmatrix.trans ----
    const int matk = (lane >> 3) & 1, matn = lane >> 4;
    #pragma unroll
    for (int ck = 0; ck < 4; ck++) {
        if (MODE == 1 && ck > w) continue;
        if (MODE == 2 && ck < w) continue;
        uint32_t A0 = ph[2*ck], A1 = phB[2*ck], A2 = ph[2*ck+1], A3 = phB[2*ck+1];
        uint32_t L0 = pl[2*ck], L1 = plB[2*ck], L2 = pl[2*ck+1], L3 = plB[2*ck+1];
        uint32_t rowoff = (uint32_t)((ck * 16 + matk * 8 + rk) * 128);
        #pragma unroll
        for (int ntd = 0; ntd < 8; ntd += 2) {
            uint32_t base = sb + rowoff + ((uint32_t)((ntd + matn) * 16) ^ xorl);
            uint32_t vh0, vh1, vh2, vh3, vl0, vl1, vl2, vl3;
            ldsm4t(vh0, vh1, vh2, vh3, base + VH);
            ldsm4t(vl0, vl1, vl2, vl3, base + VL);
            mma4(o[ntd],     A0, A1, A2, A3, vh0, vh1);
            mma4(o[ntd + 1], A0, A1, A2, A3, vh2, vh3);
            mma4(o[ntd],     L0, L1, L2, L3, vh0, vh1);
            mma4(o[ntd + 1], L0, L1, L2, L3, vh2, vh3);
            mma4(o[ntd],     A0, A1, A2, A3, vl0, vl1);
            mma4(o[ntd + 1], A0, A1, A2, A3, vl2, vl3);
        }
    }
}

__global__ __launch_bounds__(128, 3) void swa_mma(const float* __restrict__ qkv,
                                                  float* __restrict__ out)
{
    extern __shared__ __align__(1024) char smc[];
    const uint32_t sbu = smem_u32(smc);
    const int tid = threadIdx.x, lane = tid & 31, w = tid >> 5;
    const int g = lane >> 2, t = lane & 3;
    const int b = blockIdx.y, q0 = blockIdx.x * TQ;
    const float* qkv_b = qkv + (size_t)b * SEQ * 192;

    const int iq0 = q0 + w * 16 + g, iq1 = iq0 + 8;

    // ---- load Q fragments, scaled, split bf16 hi/lo ----
    const float SCL = 0.125f * 1.44269504088896f;   // 1/sqrt(64) * log2(e)
    uint32_t qh[4][4], ql[4][4];
    {
        const float* qp0 = qkv_b + (size_t)iq0 * 192;
        const float* qp1 = qkv_b + (size_t)iq1 * 192;
        #pragma unroll
        for (int c = 0; c < 4; c++) {
            float2 x0 = *reinterpret_cast<const float2*>(qp0 + c * 16 + 2 * t);
            float2 x1 = *reinterpret_cast<const float2*>(qp1 + c * 16 + 2 * t);
            float2 x2 = *reinterpret_cast<const float2*>(qp0 + c * 16 + 2 * t + 8);
            float2 x3 = *reinterpret_cast<const float2*>(qp1 + c * 16 + 2 * t + 8);
            splitp(x0.x * SCL, x0.y * SCL, qh[c][0], ql[c][0]);
            splitp(x1.x * SCL, x1.y * SCL, qh[c][1], ql[c][1]);
            splitp(x2.x * SCL, x2.y * SCL, qh[c][2], ql[c][2]);
            splitp(x3.x * SCL, x3.y * SCL, qh[c][3], ql[c][3]);
        }
    }

    float o[8][4] = {};
    float l0 = 0.0f, l1 = 0.0f;

    const int kstart = q0 >= WIN ? q0 - WIN : 0;     // multiple of 64
    const int n = (q0 - kstart) / 64 + 1;
    const char* gkv = g_kv + ((size_t)(b * (SEQ / 64) + (kstart >> 6))) * BUF;

    prefetch_tile(sbu, gkv, tid);
    for (int j = 0; j < n; j++) {
        asm volatile("cp.async.wait_group 0;" ::: "memory");
        __syncthreads();                 // tile j visible; buffer (j&1) free of j-2
        if (j + 1 < n)
            prefetch_tile(sbu + (uint32_t)(((j + 1) & 1) * BUF), gkv + (size_t)(j + 1) * BUF, tid);
        int k0 = kstart + 64 * j;
        uint32_t sb = sbu + (uint32_t)((j & 1) * BUF);
        if (q0 >= WIN && j == 0)
            compute_tile<2>(k0, tid, sb, qh, ql, o, l0, l1, iq0, iq1);
        else if (k0 == q0)
            compute_tile<1>(k0, tid, sb, qh, ql, o, l0, l1, iq0, iq1);
        else
            compute_tile<0>(k0, tid, sb, qh, ql, o, l0, l1, iq0, iq1);
        __syncthreads();                 // all warps done with tile j before overwrite
    }

    // ---- reduce l across the 4 lanes sharing a row, scale, store ----
    l0 += __shfl_xor_sync(0xffffffffu, l0, 1);
    l0 += __shfl_xor_sync(0xffffffffu, l0, 2);
    l1 += __shfl_xor_sync(0xffffffffu, l1, 1);
    l1 += __shfl_xor_sync(0xffffffffu, l1, 2);
    float rl0 = 1.0f / l0, rl1 = 1.0f / l1;

    float* o0 = out + (size_t)(b * SEQ + iq0) * 64 + 2 * t;
    float* o1 = out + (size_t)(b * SEQ + iq1) * 64 + 2 * t;
    #pragma unroll
    for (int nt = 0; nt < 8; nt++) {
        *reinterpret_cast<float2*>(o0 + nt * 8) = make_float2(o[nt][0] * rl0, o[nt][1] * rl0);
        *reinterpret_cast<float2*>(o1 + nt * 8) = make_float2(o[nt][2] * rl1, o[nt][3] * rl1);
    }
}

extern "C" void kernel_launch(void* const* d_in, const int* in_sizes, int n_in,
                              void* d_out, int out_size)
{
    const float* qkv = (const float*)d_in[0];
    float* out = (float*)d_out;
    int B = in_sizes[0] / (SEQ * 192);
    static bool configured = false;
    if (!configured) {
        cudaFuncSetAttribute(swa_mma, cudaFuncAttributeMaxDynamicSharedMemorySize, SMEM_TOTAL);
        configured = true;
    }
    dim3 cgrid(SEQ / 64, B);
    conv_kernel<<<cgrid, 128>>>(qkv);
    dim3 grid(SEQ / TQ, B);
    swa_mma<<<grid, 128, SMEM_TOTAL>>>(qkv, out);
}